// round 2
// baseline (speedup 1.0000x reference)
#include <cuda_runtime.h>

#define EPSF 1e-8f
#define BMAX 32
#define BNMAX (32 * 4096)

// -------- scratch (allocation-free: __device__ globals) --------
__device__ float g_cs1[BNMAX];   // raw cos(at_addr, addresses)   per (b,n)
__device__ float g_cs2[BNMAX];   // raw cos(fn_addr, addresses)   per (b,n)
__device__ float g_alp[BNMAX];   // clamped cos(param_addr, addresses)
__device__ float g_cs4[BNMAX];   // raw cos(body_addr, addresses)
// 10 reduced [B,D] vectors:
// 0=fn_addr 1=arg_addr 2=param_addr 3=body_addr 4=a_tag 5=a_l 6=a_r 7=b_tag 8=b_l 9=b_r
__device__ float g_vec[10][BMAX][128];

// -------- helpers --------
__device__ __forceinline__ float wsum(float v) {
#pragma unroll
    for (int m = 16; m > 0; m >>= 1) v += __shfl_xor_sync(0xffffffffu, v, m);
    return v;
}
__device__ __forceinline__ float dot4(const float4& a, const float4& b) {
    return a.x * b.x + a.y * b.y + a.z * b.z + a.w * b.w;
}
__device__ __forceinline__ void acc4(float4& acc, float s, const float4& v) {
    acc.x += s * v.x; acc.y += s * v.y; acc.z += s * v.z; acc.w += s * v.w;
}
__device__ __forceinline__ float4 mix4(float wa, const float4& a, float wb, const float4& b) {
    return make_float4(wa * a.x + wb * b.x, wa * a.y + wb * b.y,
                       wa * a.z + wb * b.z, wa * a.w + wb * b.w);
}

// -------- zero the vector accumulators (run at start of every launch) --------
__global__ void k_zero() {
    int i = blockIdx.x * blockDim.x + threadIdx.x;
    if (i < 10 * BMAX * 128) (&g_vec[0][0][0])[i] = 0.f;
}

// ============ K0: cs1 = cos(at_addr, addresses); fn += cs1*col1; arg += cs1*col2 ============
__global__ void __launch_bounds__(256) k_stage0(
    const float* __restrict__ at, const float* __restrict__ addr,
    const float* __restrict__ c1, const float* __restrict__ c2, int N)
{
    const int b = blockIdx.y;
    const int lane = threadIdx.x & 31;
    const int w = threadIdx.x >> 5;
    float4 q = reinterpret_cast<const float4*>(at)[b * 32 + lane];
    float nq = sqrtf(wsum(dot4(q, q)));
    float4 af = make_float4(0, 0, 0, 0), aa = make_float4(0, 0, 0, 0);
    int row0 = blockIdx.x * 64;
    int rend = min(row0 + 64, N);
    for (int r = row0 + w; r < rend; r += 8) {
        size_t off = ((size_t)(b * N + r)) * 32 + lane;
        float4 a  = reinterpret_cast<const float4*>(addr)[off];
        float4 v1 = reinterpret_cast<const float4*>(c1)[off];
        float4 v2 = reinterpret_cast<const float4*>(c2)[off];
        float dq = wsum(dot4(a, q));
        float na = sqrtf(wsum(dot4(a, a)));
        float cs = dq / fmaxf(na * nq, EPSF);
        if (lane == 0) g_cs1[b * N + r] = cs;
        acc4(af, cs, v1);
        acc4(aa, cs, v2);
    }
    __shared__ float sf[128], sa[128];
    if (threadIdx.x < 128) { sf[threadIdx.x] = 0.f; sa[threadIdx.x] = 0.f; }
    __syncthreads();
    int base = lane * 4;
    atomicAdd(&sf[base + 0], af.x); atomicAdd(&sf[base + 1], af.y);
    atomicAdd(&sf[base + 2], af.z); atomicAdd(&sf[base + 3], af.w);
    atomicAdd(&sa[base + 0], aa.x); atomicAdd(&sa[base + 1], aa.y);
    atomicAdd(&sa[base + 2], aa.z); atomicAdd(&sa[base + 3], aa.w);
    __syncthreads();
    if (threadIdx.x < 128) {
        atomicAdd(&g_vec[0][b][threadIdx.x], sf[threadIdx.x]);
        atomicAdd(&g_vec[1][b][threadIdx.x], sa[threadIdx.x]);
    }
}

// ============ K1: cs2=cos(fn,·), cs3=cos(arg,·); param+=cs2*c1; body+=cs2*c2;
//                  a_tag+=cs3*tags; a_l+=cs3*c1; a_r+=cs3*c2 (fn_tag is dead) ============
__global__ void __launch_bounds__(256) k_stage1(
    const float* __restrict__ addr, const float* __restrict__ tg,
    const float* __restrict__ c1, const float* __restrict__ c2, int N)
{
    const int b = blockIdx.y;
    const int lane = threadIdx.x & 31;
    const int w = threadIdx.x >> 5;
    float4 qf = reinterpret_cast<const float4*>(&g_vec[0][b][0])[lane];
    float4 qa = reinterpret_cast<const float4*>(&g_vec[1][b][0])[lane];
    float nf  = sqrtf(wsum(dot4(qf, qf)));
    float nag = sqrtf(wsum(dot4(qa, qa)));
    float4 aP = make_float4(0,0,0,0), aB = make_float4(0,0,0,0);
    float4 aT = make_float4(0,0,0,0), aL = make_float4(0,0,0,0), aR = make_float4(0,0,0,0);
    int row0 = blockIdx.x * 64;
    int rend = min(row0 + 64, N);
    for (int r = row0 + w; r < rend; r += 8) {
        size_t off = ((size_t)(b * N + r)) * 32 + lane;
        float4 a  = reinterpret_cast<const float4*>(addr)[off];
        float4 vt = reinterpret_cast<const float4*>(tg)[off];
        float4 v1 = reinterpret_cast<const float4*>(c1)[off];
        float4 v2 = reinterpret_cast<const float4*>(c2)[off];
        float df = wsum(dot4(a, qf));
        float da = wsum(dot4(a, qa));
        float nr = sqrtf(wsum(dot4(a, a)));
        float cs2 = df / fmaxf(nr * nf, EPSF);
        float cs3 = da / fmaxf(nr * nag, EPSF);
        if (lane == 0) g_cs2[b * N + r] = cs2;
        acc4(aT, cs3, vt);
        acc4(aP, cs2, v1); acc4(aL, cs3, v1);
        acc4(aB, cs2, v2); acc4(aR, cs3, v2);
    }
    __shared__ float s[5][128];
    for (int j = threadIdx.x; j < 5 * 128; j += 256) (&s[0][0])[j] = 0.f;
    __syncthreads();
    int base = lane * 4;
    atomicAdd(&s[0][base+0], aP.x); atomicAdd(&s[0][base+1], aP.y); atomicAdd(&s[0][base+2], aP.z); atomicAdd(&s[0][base+3], aP.w);
    atomicAdd(&s[1][base+0], aB.x); atomicAdd(&s[1][base+1], aB.y); atomicAdd(&s[1][base+2], aB.z); atomicAdd(&s[1][base+3], aB.w);
    atomicAdd(&s[2][base+0], aT.x); atomicAdd(&s[2][base+1], aT.y); atomicAdd(&s[2][base+2], aT.z); atomicAdd(&s[2][base+3], aT.w);
    atomicAdd(&s[3][base+0], aL.x); atomicAdd(&s[3][base+1], aL.y); atomicAdd(&s[3][base+2], aL.z); atomicAdd(&s[3][base+3], aL.w);
    atomicAdd(&s[4][base+0], aR.x); atomicAdd(&s[4][base+1], aR.y); atomicAdd(&s[4][base+2], aR.z); atomicAdd(&s[4][base+3], aR.w);
    __syncthreads();
    if (threadIdx.x < 128) {
        atomicAdd(&g_vec[2][b][threadIdx.x], s[0][threadIdx.x]); // param_addr
        atomicAdd(&g_vec[3][b][threadIdx.x], s[1][threadIdx.x]); // body_addr
        atomicAdd(&g_vec[4][b][threadIdx.x], s[2][threadIdx.x]); // a_tag
        atomicAdd(&g_vec[5][b][threadIdx.x], s[3][threadIdx.x]); // a_l
        atomicAdd(&g_vec[6][b][threadIdx.x], s[4][threadIdx.x]); // a_r
    }
}

// ============ K2: fused kv_insert(param_addr) on tags/col1/col2 + replace on col1/col2 ============
__global__ void __launch_bounds__(256) k_stage2(
    const float* __restrict__ addr, const float* __restrict__ tg,
    const float* __restrict__ c1, const float* __restrict__ c2,
    float* __restrict__ ot, float* __restrict__ o1, float* __restrict__ o2, int N)
{
    const int b = blockIdx.y;
    const int lane = threadIdx.x & 31;
    const int w = threadIdx.x >> 5;
    float4 qp   = reinterpret_cast<const float4*>(&g_vec[2][b][0])[lane];
    float4 qarg = reinterpret_cast<const float4*>(&g_vec[1][b][0])[lane];
    float4 qtag = reinterpret_cast<const float4*>(&g_vec[4][b][0])[lane];
    float4 qal  = reinterpret_cast<const float4*>(&g_vec[5][b][0])[lane];
    float4 qar  = reinterpret_cast<const float4*>(&g_vec[6][b][0])[lane];
    float np = sqrtf(wsum(dot4(qp, qp)));
    int row0 = blockIdx.x * 64;
    int rend = min(row0 + 64, N);
    for (int r = row0 + w; r < rend; r += 8) {
        size_t off = ((size_t)(b * N + r)) * 32 + lane;
        float4 a  = reinterpret_cast<const float4*>(addr)[off];
        float4 vt = reinterpret_cast<const float4*>(tg)[off];
        float4 v1 = reinterpret_cast<const float4*>(c1)[off];
        float4 v2 = reinterpret_cast<const float4*>(c2)[off];
        float dp = wsum(dot4(a, qp));
        float nr = sqrtf(wsum(dot4(a, a)));
        float alr = dp / fmaxf(nr * np, EPSF);
        float alpha = (alr > EPSF) ? alr : 0.f;
        if (lane == 0) g_alp[b * N + r] = alpha;
        float ia = 1.f - alpha;
        // tags: insert only
        reinterpret_cast<float4*>(ot)[off] = mix4(ia, vt, alpha, qtag);
        // col1: insert then replace (row lives in registers)
        float4 u = mix4(ia, v1, alpha, qal);
        float du = wsum(dot4(u, qp));
        float nu = sqrtf(wsum(dot4(u, u)));
        float sim = du / fmaxf(nu * np, EPSF);
        reinterpret_cast<float4*>(o1)[off] = mix4(1.f - sim, u, sim, qarg);
        // col2: insert then replace
        u = mix4(ia, v2, alpha, qar);
        du = wsum(dot4(u, qp));
        nu = sqrtf(wsum(dot4(u, u)));
        sim = du / fmaxf(nu * np, EPSF);
        reinterpret_cast<float4*>(o2)[off] = mix4(1.f - sim, u, sim, qarg);
    }
}

// ============ K3: cs4 = cos(body_addr, addresses); b_* += cs4 * updated arrays ============
__global__ void __launch_bounds__(256) k_stage3(
    const float* __restrict__ addr, const float* __restrict__ ot,
    const float* __restrict__ o1, const float* __restrict__ o2, int N)
{
    const int b = blockIdx.y;
    const int lane = threadIdx.x & 31;
    const int w = threadIdx.x >> 5;
    float4 qb = reinterpret_cast<const float4*>(&g_vec[3][b][0])[lane];
    float nb = sqrtf(wsum(dot4(qb, qb)));
    float4 aT = make_float4(0,0,0,0), aL = make_float4(0,0,0,0), aR = make_float4(0,0,0,0);
    int row0 = blockIdx.x * 64;
    int rend = min(row0 + 64, N);
    for (int r = row0 + w; r < rend; r += 8) {
        size_t off = ((size_t)(b * N + r)) * 32 + lane;
        float4 a  = reinterpret_cast<const float4*>(addr)[off];
        float4 vt = reinterpret_cast<const float4*>(ot)[off];
        float4 v1 = reinterpret_cast<const float4*>(o1)[off];
        float4 v2 = reinterpret_cast<const float4*>(o2)[off];
        float db = wsum(dot4(a, qb));
        float nr = sqrtf(wsum(dot4(a, a)));
        float cs4 = db / fmaxf(nr * nb, EPSF);
        if (lane == 0) g_cs4[b * N + r] = cs4;
        acc4(aT, cs4, vt); acc4(aL, cs4, v1); acc4(aR, cs4, v2);
    }
    __shared__ float s[3][128];
    for (int j = threadIdx.x; j < 3 * 128; j += 256) (&s[0][0])[j] = 0.f;
    __syncthreads();
    int base = lane * 4;
    atomicAdd(&s[0][base+0], aT.x); atomicAdd(&s[0][base+1], aT.y); atomicAdd(&s[0][base+2], aT.z); atomicAdd(&s[0][base+3], aT.w);
    atomicAdd(&s[1][base+0], aL.x); atomicAdd(&s[1][base+1], aL.y); atomicAdd(&s[1][base+2], aL.z); atomicAdd(&s[1][base+3], aL.w);
    atomicAdd(&s[2][base+0], aR.x); atomicAdd(&s[2][base+1], aR.y); atomicAdd(&s[2][base+2], aR.z); atomicAdd(&s[2][base+3], aR.w);
    __syncthreads();
    if (threadIdx.x < 128) {
        atomicAdd(&g_vec[7][b][threadIdx.x], s[0][threadIdx.x]); // b_tag
        atomicAdd(&g_vec[8][b][threadIdx.x], s[1][threadIdx.x]); // b_l
        atomicAdd(&g_vec[9][b][threadIdx.x], s[2][threadIdx.x]); // b_r
    }
}

// ============ K4: kv_insert(at_addr) with b_* + closed-form GC, elementwise ============
__global__ void __launch_bounds__(256) k_stage4(
    const float* __restrict__ zv, const int* __restrict__ gsp,
    float* __restrict__ ot, float* __restrict__ o1, float* __restrict__ o2,
    int B, int N)
{
    int i = blockIdx.x * blockDim.x + threadIdx.x;   // float4 index
    int total = B * N * 32;
    if (i >= total) return;
    int d4 = i & 31;
    int bn = i >> 5;
    int b = bn / N;
    float a = g_cs1[bn];  a  = (a  > EPSF) ? a  : 0.f;
    float cf = g_cs2[bn]; cf = (cf > EPSF) ? cf : 0.f;
    float cp = g_alp[bn];
    float cb = g_cs4[bn]; cb = (cb > EPSF) ? cb : 0.f;
    float base = (1.f - cf) * (1.f - cp) * (1.f - cb);
    int g = *gsp;
    float P = 1.f;
    for (int k = 0; k < g; k++) P *= base;
    float ia = 1.f - a, iP = 1.f - P;
    float4 z  = reinterpret_cast<const float4*>(zv)[d4];
    float4 bt = reinterpret_cast<const float4*>(&g_vec[7][b][0])[d4];
    float4 bl = reinterpret_cast<const float4*>(&g_vec[8][b][0])[d4];
    float4 br = reinterpret_cast<const float4*>(&g_vec[9][b][0])[d4];

    float4 t = reinterpret_cast<float4*>(ot)[i];
    t = mix4(ia, t, a, bt);
    reinterpret_cast<float4*>(ot)[i] = mix4(P, t, iP, z);

    t = reinterpret_cast<float4*>(o1)[i];
    t = mix4(ia, t, a, bl);
    reinterpret_cast<float4*>(o1)[i] = mix4(P, t, iP, z);

    t = reinterpret_cast<float4*>(o2)[i];
    t = mix4(ia, t, a, br);
    reinterpret_cast<float4*>(o2)[i] = mix4(P, t, iP, z);
}

// ============ launch ============
extern "C" void kernel_launch(void* const* d_in, const int* in_sizes, int n_in,
                              void* d_out, int out_size)
{
    const float* at   = (const float*)d_in[0];  // [B,D]
    const float* addr = (const float*)d_in[1];  // [B,N,D]
    const float* tg   = (const float*)d_in[2];  // [B,N,D]
    const float* c1   = (const float*)d_in[3];  // [B,N,D]
    const float* c2   = (const float*)d_in[4];  // [B,N,D]
    const float* zv   = (const float*)d_in[5];  // [D]
    const int*   gs   = (const int*)d_in[6];    // scalar

    int D = in_sizes[5];                 // 128
    int B = in_sizes[0] / D;             // 32
    int N = in_sizes[1] / in_sizes[0];   // 2048

    size_t stride = (size_t)B * N * D;
    float* ot = (float*)d_out;
    float* o1 = ot + stride;
    float* o2 = o1 + stride;

    k_zero<<<(10 * BMAX * 128 + 255) / 256, 256>>>();

    dim3 grid((N + 63) / 64, B);
    k_stage0<<<grid, 256>>>(at, addr, c1, c2, N);
    k_stage1<<<grid, 256>>>(addr, tg, c1, c2, N);
    k_stage2<<<grid, 256>>>(addr, tg, c1, c2, ot, o1, o2, N);
    k_stage3<<<grid, 256>>>(addr, ot, o1, o2, N);

    int tot4 = B * N * (D / 4);
    k_stage4<<<(tot4 + 255) / 256, 256>>>(zv, gs, ot, o1, o2, B, N);

    (void)n_in; (void)out_size;
}

// round 3
// speedup vs baseline: 1.0784x; 1.0784x over previous
#include <cuda_runtime.h>

#define EPSF 1e-8f
#define BMAX 32
#define BNMAX (32 * 4096)

// -------- scratch (allocation-free: __device__ globals) --------
__device__ float g_cs1[BNMAX];   // raw cos(at_addr, addresses)
__device__ float g_cs2[BNMAX];   // raw cos(fn_addr, addresses)
__device__ float g_alp[BNMAX];   // clamped cos(param_addr, addresses)
__device__ float g_cs4[BNMAX];   // raw cos(body_addr, addresses)
__device__ float g_s1[BNMAX];    // replace sim for col1
__device__ float g_s2[BNMAX];    // replace sim for col2
__device__ float g_nrm[BNMAX];   // ||addresses row||
// 10 reduced [B,D] vectors:
// 0=fn_addr 1=arg_addr 2=param_addr 3=body_addr 4=a_tag 5=a_l 6=a_r 7=b_tag 8=b_l 9=b_r
__device__ float g_vec[10][BMAX][128];

// -------- helpers --------
__device__ __forceinline__ float wsum(float v) {
#pragma unroll
    for (int m = 16; m > 0; m >>= 1) v += __shfl_xor_sync(0xffffffffu, v, m);
    return v;
}
__device__ __forceinline__ float dot4(const float4& a, const float4& b) {
    return a.x * b.x + a.y * b.y + a.z * b.z + a.w * b.w;
}
__device__ __forceinline__ void acc4(float4& acc, float s, const float4& v) {
    acc.x += s * v.x; acc.y += s * v.y; acc.z += s * v.z; acc.w += s * v.w;
}
__device__ __forceinline__ float4 mix4(float wa, const float4& a, float wb, const float4& b) {
    return make_float4(wa * a.x + wb * b.x, wa * a.y + wb * b.y,
                       wa * a.z + wb * b.z, wa * a.w + wb * b.w);
}

__global__ void k_zero() {
    int i = blockIdx.x * blockDim.x + threadIdx.x;
    if (i < 10 * BMAX * 128) (&g_vec[0][0][0])[i] = 0.f;
}

// ============ K0: cs1 = cos(at, addr); fn += cs1*c1; arg += cs1*c2; store ||addr row|| ============
__global__ void __launch_bounds__(256) k_stage0(
    const float* __restrict__ at, const float* __restrict__ addr,
    const float* __restrict__ c1, const float* __restrict__ c2, int N)
{
    const int b = blockIdx.y;
    const int lane = threadIdx.x & 31;
    const int w = threadIdx.x >> 5;
    float4 q = reinterpret_cast<const float4*>(at)[b * 32 + lane];
    float nq = sqrtf(wsum(dot4(q, q)));
    float4 af = make_float4(0, 0, 0, 0), aa = make_float4(0, 0, 0, 0);
    int row0 = blockIdx.x * 64;
    int rend = min(row0 + 64, N);
    for (int r = row0 + w; r < rend; r += 8) {
        size_t off = ((size_t)(b * N + r)) * 32 + lane;
        float4 a  = reinterpret_cast<const float4*>(addr)[off];
        float4 v1 = reinterpret_cast<const float4*>(c1)[off];
        float4 v2 = reinterpret_cast<const float4*>(c2)[off];
        float dq = wsum(dot4(a, q));
        float na = sqrtf(wsum(dot4(a, a)));
        float cs = dq / fmaxf(na * nq, EPSF);
        if (lane == 0) { g_cs1[b * N + r] = cs; g_nrm[b * N + r] = na; }
        acc4(af, cs, v1);
        acc4(aa, cs, v2);
    }
    __shared__ float sf[128], sa[128];
    if (threadIdx.x < 128) { sf[threadIdx.x] = 0.f; sa[threadIdx.x] = 0.f; }
    __syncthreads();
    int base = lane * 4;
    atomicAdd(&sf[base + 0], af.x); atomicAdd(&sf[base + 1], af.y);
    atomicAdd(&sf[base + 2], af.z); atomicAdd(&sf[base + 3], af.w);
    atomicAdd(&sa[base + 0], aa.x); atomicAdd(&sa[base + 1], aa.y);
    atomicAdd(&sa[base + 2], aa.z); atomicAdd(&sa[base + 3], aa.w);
    __syncthreads();
    if (threadIdx.x < 128) {
        atomicAdd(&g_vec[0][b][threadIdx.x], sf[threadIdx.x]);
        atomicAdd(&g_vec[1][b][threadIdx.x], sa[threadIdx.x]);
    }
}

// ============ K1: cs2=cos(fn,·), cs3=cos(arg,·); param+=cs2*c1; body+=cs2*c2;
//                  a_tag+=cs3*tg; a_l+=cs3*c1; a_r+=cs3*c2 ============
__global__ void __launch_bounds__(256) k_stage1(
    const float* __restrict__ addr, const float* __restrict__ tg,
    const float* __restrict__ c1, const float* __restrict__ c2, int N)
{
    const int b = blockIdx.y;
    const int lane = threadIdx.x & 31;
    const int w = threadIdx.x >> 5;
    float4 qf = reinterpret_cast<const float4*>(&g_vec[0][b][0])[lane];
    float4 qa = reinterpret_cast<const float4*>(&g_vec[1][b][0])[lane];
    float nf  = sqrtf(wsum(dot4(qf, qf)));
    float nag = sqrtf(wsum(dot4(qa, qa)));
    float4 aP = make_float4(0,0,0,0), aB = make_float4(0,0,0,0);
    float4 aT = make_float4(0,0,0,0), aL = make_float4(0,0,0,0), aR = make_float4(0,0,0,0);
    int row0 = blockIdx.x * 64;
    int rend = min(row0 + 64, N);
    for (int r = row0 + w; r < rend; r += 8) {
        size_t off = ((size_t)(b * N + r)) * 32 + lane;
        float4 a  = reinterpret_cast<const float4*>(addr)[off];
        float4 vt = reinterpret_cast<const float4*>(tg)[off];
        float4 v1 = reinterpret_cast<const float4*>(c1)[off];
        float4 v2 = reinterpret_cast<const float4*>(c2)[off];
        float nr = g_nrm[b * N + r];
        float df = wsum(dot4(a, qf));
        float da = wsum(dot4(a, qa));
        float cs2 = df / fmaxf(nr * nf, EPSF);
        float cs3 = da / fmaxf(nr * nag, EPSF);
        if (lane == 0) g_cs2[b * N + r] = cs2;
        acc4(aT, cs3, vt);
        acc4(aP, cs2, v1); acc4(aL, cs3, v1);
        acc4(aB, cs2, v2); acc4(aR, cs3, v2);
    }
    __shared__ float s[5][128];
    for (int j = threadIdx.x; j < 5 * 128; j += 256) (&s[0][0])[j] = 0.f;
    __syncthreads();
    int base = lane * 4;
    atomicAdd(&s[0][base+0], aP.x); atomicAdd(&s[0][base+1], aP.y); atomicAdd(&s[0][base+2], aP.z); atomicAdd(&s[0][base+3], aP.w);
    atomicAdd(&s[1][base+0], aB.x); atomicAdd(&s[1][base+1], aB.y); atomicAdd(&s[1][base+2], aB.z); atomicAdd(&s[1][base+3], aB.w);
    atomicAdd(&s[2][base+0], aT.x); atomicAdd(&s[2][base+1], aT.y); atomicAdd(&s[2][base+2], aT.z); atomicAdd(&s[2][base+3], aT.w);
    atomicAdd(&s[3][base+0], aL.x); atomicAdd(&s[3][base+1], aL.y); atomicAdd(&s[3][base+2], aL.z); atomicAdd(&s[3][base+3], aL.w);
    atomicAdd(&s[4][base+0], aR.x); atomicAdd(&s[4][base+1], aR.y); atomicAdd(&s[4][base+2], aR.z); atomicAdd(&s[4][base+3], aR.w);
    __syncthreads();
    if (threadIdx.x < 128) {
        atomicAdd(&g_vec[2][b][threadIdx.x], s[0][threadIdx.x]); // param_addr
        atomicAdd(&g_vec[3][b][threadIdx.x], s[1][threadIdx.x]); // body_addr
        atomicAdd(&g_vec[4][b][threadIdx.x], s[2][threadIdx.x]); // a_tag
        atomicAdd(&g_vec[5][b][threadIdx.x], s[3][threadIdx.x]); // a_l
        atomicAdd(&g_vec[6][b][threadIdx.x], s[4][threadIdx.x]); // a_r
    }
}

// ============ K2': fused insert(param)+replace+select(body) — scalar outputs only ============
// Computes updated rows in registers, writes per-row scalars (alpha, s1, s2, cs4)
// and accumulates b_tag/b_l/b_r. No 96MB intermediate write.
__global__ void __launch_bounds__(256) k_stage2(
    const float* __restrict__ addr, const float* __restrict__ tg,
    const float* __restrict__ c1, const float* __restrict__ c2, int N)
{
    const int b = blockIdx.y;
    const int lane = threadIdx.x & 31;
    const int w = threadIdx.x >> 5;
    float4 qp   = reinterpret_cast<const float4*>(&g_vec[2][b][0])[lane];
    float4 qb   = reinterpret_cast<const float4*>(&g_vec[3][b][0])[lane];
    float4 qarg = reinterpret_cast<const float4*>(&g_vec[1][b][0])[lane];
    float4 qtag = reinterpret_cast<const float4*>(&g_vec[4][b][0])[lane];
    float4 qal  = reinterpret_cast<const float4*>(&g_vec[5][b][0])[lane];
    float4 qar  = reinterpret_cast<const float4*>(&g_vec[6][b][0])[lane];
    float np = sqrtf(wsum(dot4(qp, qp)));
    float nb = sqrtf(wsum(dot4(qb, qb)));
    float4 aT = make_float4(0,0,0,0), aL = make_float4(0,0,0,0), aR = make_float4(0,0,0,0);
    int row0 = blockIdx.x * 64;
    int rend = min(row0 + 64, N);
    for (int r = row0 + w; r < rend; r += 8) {
        size_t off = ((size_t)(b * N + r)) * 32 + lane;
        float4 a  = reinterpret_cast<const float4*>(addr)[off];
        float4 vt = reinterpret_cast<const float4*>(tg)[off];
        float4 v1 = reinterpret_cast<const float4*>(c1)[off];
        float4 v2 = reinterpret_cast<const float4*>(c2)[off];
        float nr = g_nrm[b * N + r];
        float dp = wsum(dot4(a, qp));
        float db = wsum(dot4(a, qb));
        float alr = dp / fmaxf(nr * np, EPSF);
        float alpha = (alr > EPSF) ? alr : 0.f;
        float cs4 = db / fmaxf(nr * nb, EPSF);
        float ia = 1.f - alpha;
        // updated rows (registers only)
        float4 ut = mix4(ia, vt, alpha, qtag);
        float4 u1 = mix4(ia, v1, alpha, qal);
        float4 u2 = mix4(ia, v2, alpha, qar);
        float du1 = wsum(dot4(u1, qp));
        float nu1 = sqrtf(wsum(dot4(u1, u1)));
        float du2 = wsum(dot4(u2, qp));
        float nu2 = sqrtf(wsum(dot4(u2, u2)));
        float s1 = du1 / fmaxf(nu1 * np, EPSF);
        float s2 = du2 / fmaxf(nu2 * np, EPSF);
        float4 o1v = mix4(1.f - s1, u1, s1, qarg);
        float4 o2v = mix4(1.f - s2, u2, s2, qarg);
        if (lane == 0) {
            int bn = b * N + r;
            g_alp[bn] = alpha; g_s1[bn] = s1; g_s2[bn] = s2; g_cs4[bn] = cs4;
        }
        acc4(aT, cs4, ut); acc4(aL, cs4, o1v); acc4(aR, cs4, o2v);
    }
    __shared__ float s[3][128];
    for (int j = threadIdx.x; j < 3 * 128; j += 256) (&s[0][0])[j] = 0.f;
    __syncthreads();
    int base = lane * 4;
    atomicAdd(&s[0][base+0], aT.x); atomicAdd(&s[0][base+1], aT.y); atomicAdd(&s[0][base+2], aT.z); atomicAdd(&s[0][base+3], aT.w);
    atomicAdd(&s[1][base+0], aL.x); atomicAdd(&s[1][base+1], aL.y); atomicAdd(&s[1][base+2], aL.z); atomicAdd(&s[1][base+3], aL.w);
    atomicAdd(&s[2][base+0], aR.x); atomicAdd(&s[2][base+1], aR.y); atomicAdd(&s[2][base+2], aR.z); atomicAdd(&s[2][base+3], aR.w);
    __syncthreads();
    if (threadIdx.x < 128) {
        atomicAdd(&g_vec[7][b][threadIdx.x], s[0][threadIdx.x]); // b_tag
        atomicAdd(&g_vec[8][b][threadIdx.x], s[1][threadIdx.x]); // b_l
        atomicAdd(&g_vec[9][b][threadIdx.x], s[2][threadIdx.x]); // b_r
    }
}

// ============ K3': reconstruct rows from inputs + insert(at, b_*) + closed-form GC ============
__global__ void __launch_bounds__(256) k_stage3(
    const float* __restrict__ tg, const float* __restrict__ c1, const float* __restrict__ c2,
    const float* __restrict__ zv, const int* __restrict__ gsp,
    float* __restrict__ ot, float* __restrict__ o1, float* __restrict__ o2,
    int B, int N)
{
    int i = blockIdx.x * blockDim.x + threadIdx.x;   // float4 index
    int total = B * N * 32;
    if (i >= total) return;
    int d4 = i & 31;
    int bn = i >> 5;
    int b = bn / N;
    // per-row scalars
    float a1 = g_cs1[bn]; a1 = (a1 > EPSF) ? a1 : 0.f;       // insert(at) alpha
    float cf = g_cs2[bn]; cf = (cf > EPSF) ? cf : 0.f;       // GC fn alpha
    float cp = g_alp[bn];                                    // insert(param) alpha (clamped)
    float cb = g_cs4[bn]; cb = (cb > EPSF) ? cb : 0.f;       // GC body alpha
    float s1 = g_s1[bn], s2 = g_s2[bn];
    float base = (1.f - cf) * (1.f - cp) * (1.f - cb);
    int g = *gsp;
    float P = 1.f;
    for (int k = 0; k < g; k++) P *= base;
    float ia1 = 1.f - a1, icp = 1.f - cp, iP = 1.f - P;
    // constant [D] vectors
    float4 z    = reinterpret_cast<const float4*>(zv)[d4];
    float4 qarg = reinterpret_cast<const float4*>(&g_vec[1][b][0])[d4];
    float4 qtag = reinterpret_cast<const float4*>(&g_vec[4][b][0])[d4];
    float4 qal  = reinterpret_cast<const float4*>(&g_vec[5][b][0])[d4];
    float4 qar  = reinterpret_cast<const float4*>(&g_vec[6][b][0])[d4];
    float4 bt   = reinterpret_cast<const float4*>(&g_vec[7][b][0])[d4];
    float4 bl   = reinterpret_cast<const float4*>(&g_vec[8][b][0])[d4];
    float4 br   = reinterpret_cast<const float4*>(&g_vec[9][b][0])[d4];

    // tags
    float4 t = reinterpret_cast<const float4*>(tg)[i];
    t = mix4(icp, t, cp, qtag);                 // insert(param, a_tag)
    t = mix4(ia1, t, a1, bt);                   // insert(at, b_tag)
    reinterpret_cast<float4*>(ot)[i] = mix4(P, t, iP, z);   // GC

    // col1
    t = reinterpret_cast<const float4*>(c1)[i];
    t = mix4(icp, t, cp, qal);                  // insert(param, a_l)
    t = mix4(1.f - s1, t, s1, qarg);            // replace
    t = mix4(ia1, t, a1, bl);                   // insert(at, b_l)
    reinterpret_cast<float4*>(o1)[i] = mix4(P, t, iP, z);

    // col2
    t = reinterpret_cast<const float4*>(c2)[i];
    t = mix4(icp, t, cp, qar);
    t = mix4(1.f - s2, t, s2, qarg);
    t = mix4(ia1, t, a1, br);
    reinterpret_cast<float4*>(o2)[i] = mix4(P, t, iP, z);
}

// ============ launch ============
extern "C" void kernel_launch(void* const* d_in, const int* in_sizes, int n_in,
                              void* d_out, int out_size)
{
    const float* at   = (const float*)d_in[0];  // [B,D]
    const float* addr = (const float*)d_in[1];  // [B,N,D]
    const float* tg   = (const float*)d_in[2];  // [B,N,D]
    const float* c1   = (const float*)d_in[3];  // [B,N,D]
    const float* c2   = (const float*)d_in[4];  // [B,N,D]
    const float* zv   = (const float*)d_in[5];  // [D]
    const int*   gs   = (const int*)d_in[6];    // scalar

    int D = in_sizes[5];                 // 128
    int B = in_sizes[0] / D;             // 32
    int N = in_sizes[1] / in_sizes[0];   // 2048

    size_t stride = (size_t)B * N * D;
    float* ot = (float*)d_out;
    float* o1 = ot + stride;
    float* o2 = o1 + stride;

    k_zero<<<(10 * BMAX * 128 + 255) / 256, 256>>>();

    dim3 grid((N + 63) / 64, B);
    k_stage0<<<grid, 256>>>(at, addr, c1, c2, N);
    k_stage1<<<grid, 256>>>(addr, tg, c1, c2, N);
    k_stage2<<<grid, 256>>>(addr, tg, c1, c2, N);

    int tot4 = B * N * (D / 4);
    k_stage3<<<(tot4 + 255) / 256, 256>>>(tg, c1, c2, zv, gs, ot, o1, o2, B, N);

    (void)n_in; (void)out_size;
}

// round 4
// speedup vs baseline: 1.0938x; 1.0142x over previous
#include <cuda_runtime.h>

#define EPSF 1e-8f
#define BMAX 32
#define BNMAX (32 * 4096)

// -------- scratch (allocation-free: __device__ globals) --------
__device__ float g_cs1[BNMAX];   // raw cos(at_addr, addresses)
__device__ float g_cs2[BNMAX];   // raw cos(fn_addr, addresses)
__device__ float g_alp[BNMAX];   // clamped cos(param_addr, addresses)
__device__ float g_cs4[BNMAX];   // raw cos(body_addr, addresses)
__device__ float g_s1[BNMAX];    // replace sim for col1
__device__ float g_s2[BNMAX];    // replace sim for col2
__device__ float g_nrm[BNMAX];   // ||addresses row||
// 10 reduced [B,D] vectors:
// 0=fn_addr 1=arg_addr 2=param_addr 3=body_addr 4=a_tag 5=a_l 6=a_r 7=b_tag 8=b_l 9=b_r
__device__ float g_vec[10][BMAX][128];

// -------- helpers --------
__device__ __forceinline__ float wsum(float v) {
#pragma unroll
    for (int m = 16; m > 0; m >>= 1) v += __shfl_xor_sync(0xffffffffu, v, m);
    return v;
}
__device__ __forceinline__ float dot4(const float4& a, const float4& b) {
    return a.x * b.x + a.y * b.y + a.z * b.z + a.w * b.w;
}
__device__ __forceinline__ void acc4(float4& acc, float s, const float4& v) {
    acc.x += s * v.x; acc.y += s * v.y; acc.z += s * v.z; acc.w += s * v.w;
}
__device__ __forceinline__ float4 mix4(float wa, const float4& a, float wb, const float4& b) {
    return make_float4(wa * a.x + wb * b.x, wa * a.y + wb * b.y,
                       wa * a.z + wb * b.z, wa * a.w + wb * b.w);
}

__global__ void k_zero() {
    int i = blockIdx.x * blockDim.x + threadIdx.x;
    if (i < 10 * BMAX * 128) (&g_vec[0][0][0])[i] = 0.f;
}

// ============ K0: cs1 = cos(at, addr); fn += cs1*c1; arg += cs1*c2; store ||addr row|| ============
__global__ void __launch_bounds__(256) k_stage0(
    const float* __restrict__ at, const float* __restrict__ addr,
    const float* __restrict__ c1, const float* __restrict__ c2, int N)
{
    const int b = blockIdx.y;
    const int lane = threadIdx.x & 31;
    const int w = threadIdx.x >> 5;
    float4 q = reinterpret_cast<const float4*>(at)[b * 32 + lane];
    float nq = sqrtf(wsum(dot4(q, q)));
    float4 af = make_float4(0, 0, 0, 0), aa = make_float4(0, 0, 0, 0);
    int row0 = blockIdx.x * 64;
    int rend = min(row0 + 64, N);
#pragma unroll 2
    for (int r = row0 + w; r < rend; r += 8) {
        size_t off = ((size_t)(b * N + r)) * 32 + lane;
        float4 a  = reinterpret_cast<const float4*>(addr)[off];
        float4 v1 = reinterpret_cast<const float4*>(c1)[off];
        float4 v2 = reinterpret_cast<const float4*>(c2)[off];
        float dq = wsum(dot4(a, q));
        float na = sqrtf(wsum(dot4(a, a)));
        float cs = dq / fmaxf(na * nq, EPSF);
        if (lane == 0) { g_cs1[b * N + r] = cs; g_nrm[b * N + r] = na; }
        acc4(af, cs, v1);
        acc4(aa, cs, v2);
    }
    __shared__ float sf[128], sa[128];
    if (threadIdx.x < 128) { sf[threadIdx.x] = 0.f; sa[threadIdx.x] = 0.f; }
    __syncthreads();
    int base = lane * 4;
    atomicAdd(&sf[base + 0], af.x); atomicAdd(&sf[base + 1], af.y);
    atomicAdd(&sf[base + 2], af.z); atomicAdd(&sf[base + 3], af.w);
    atomicAdd(&sa[base + 0], aa.x); atomicAdd(&sa[base + 1], aa.y);
    atomicAdd(&sa[base + 2], aa.z); atomicAdd(&sa[base + 3], aa.w);
    __syncthreads();
    if (threadIdx.x < 128) {
        atomicAdd(&g_vec[0][b][threadIdx.x], sf[threadIdx.x]);
        atomicAdd(&g_vec[1][b][threadIdx.x], sa[threadIdx.x]);
    }
}

// ============ K1: cs2=cos(fn,·), cs3=cos(arg,·); 5 weighted sums ============
__global__ void __launch_bounds__(256) k_stage1(
    const float* __restrict__ addr, const float* __restrict__ tg,
    const float* __restrict__ c1, const float* __restrict__ c2, int N)
{
    const int b = blockIdx.y;
    const int lane = threadIdx.x & 31;
    const int w = threadIdx.x >> 5;
    float4 qf = reinterpret_cast<const float4*>(&g_vec[0][b][0])[lane];
    float4 qa = reinterpret_cast<const float4*>(&g_vec[1][b][0])[lane];
    float nf  = sqrtf(wsum(dot4(qf, qf)));
    float nag = sqrtf(wsum(dot4(qa, qa)));
    float4 aP = make_float4(0,0,0,0), aB = make_float4(0,0,0,0);
    float4 aT = make_float4(0,0,0,0), aL = make_float4(0,0,0,0), aR = make_float4(0,0,0,0);
    int row0 = blockIdx.x * 64;
    int rend = min(row0 + 64, N);
#pragma unroll 2
    for (int r = row0 + w; r < rend; r += 8) {
        size_t off = ((size_t)(b * N + r)) * 32 + lane;
        float4 a  = reinterpret_cast<const float4*>(addr)[off];
        float4 vt = reinterpret_cast<const float4*>(tg)[off];
        float4 v1 = reinterpret_cast<const float4*>(c1)[off];
        float4 v2 = reinterpret_cast<const float4*>(c2)[off];
        float nr = g_nrm[b * N + r];
        float df = wsum(dot4(a, qf));
        float da = wsum(dot4(a, qa));
        float cs2 = df / fmaxf(nr * nf, EPSF);
        float cs3 = da / fmaxf(nr * nag, EPSF);
        if (lane == 0) g_cs2[b * N + r] = cs2;
        acc4(aT, cs3, vt);
        acc4(aP, cs2, v1); acc4(aL, cs3, v1);
        acc4(aB, cs2, v2); acc4(aR, cs3, v2);
    }
    __shared__ float s[5][128];
    for (int j = threadIdx.x; j < 5 * 128; j += 256) (&s[0][0])[j] = 0.f;
    __syncthreads();
    int base = lane * 4;
    atomicAdd(&s[0][base+0], aP.x); atomicAdd(&s[0][base+1], aP.y); atomicAdd(&s[0][base+2], aP.z); atomicAdd(&s[0][base+3], aP.w);
    atomicAdd(&s[1][base+0], aB.x); atomicAdd(&s[1][base+1], aB.y); atomicAdd(&s[1][base+2], aB.z); atomicAdd(&s[1][base+3], aB.w);
    atomicAdd(&s[2][base+0], aT.x); atomicAdd(&s[2][base+1], aT.y); atomicAdd(&s[2][base+2], aT.z); atomicAdd(&s[2][base+3], aT.w);
    atomicAdd(&s[3][base+0], aL.x); atomicAdd(&s[3][base+1], aL.y); atomicAdd(&s[3][base+2], aL.z); atomicAdd(&s[3][base+3], aL.w);
    atomicAdd(&s[4][base+0], aR.x); atomicAdd(&s[4][base+1], aR.y); atomicAdd(&s[4][base+2], aR.z); atomicAdd(&s[4][base+3], aR.w);
    __syncthreads();
    if (threadIdx.x < 128) {
        atomicAdd(&g_vec[2][b][threadIdx.x], s[0][threadIdx.x]); // param_addr
        atomicAdd(&g_vec[3][b][threadIdx.x], s[1][threadIdx.x]); // body_addr
        atomicAdd(&g_vec[4][b][threadIdx.x], s[2][threadIdx.x]); // a_tag
        atomicAdd(&g_vec[5][b][threadIdx.x], s[3][threadIdx.x]); // a_l
        atomicAdd(&g_vec[6][b][threadIdx.x], s[4][threadIdx.x]); // a_r
    }
}

// ============ K2: flattened insert(param)+replace+select(body) ============
// 8 INDEPENDENT per-row reductions (single shfl level); q-vector parts of the
// b_* accumulators collapse to per-block scalars applied in the epilogue.
__global__ void __launch_bounds__(256) k_stage2(
    const float* __restrict__ addr, const float* __restrict__ tg,
    const float* __restrict__ c1, const float* __restrict__ c2, int N)
{
    const int b = blockIdx.y;
    const int lane = threadIdx.x & 31;
    const int w = threadIdx.x >> 5;
    float4 qp  = reinterpret_cast<const float4*>(&g_vec[2][b][0])[lane];
    float4 qb  = reinterpret_cast<const float4*>(&g_vec[3][b][0])[lane];
    float4 qal = reinterpret_cast<const float4*>(&g_vec[5][b][0])[lane];
    float4 qar = reinterpret_cast<const float4*>(&g_vec[6][b][0])[lane];
    // per-batch constants (one-time prologue reductions)
    float np    = sqrtf(wsum(dot4(qp, qp)));
    float nb    = sqrtf(wsum(dot4(qb, qb)));
    float kalp  = wsum(dot4(qal, qp));
    float karp  = wsum(dot4(qar, qp));
    float kalal = wsum(dot4(qal, qal));
    float karar = wsum(dot4(qar, qar));

    float4 At = make_float4(0,0,0,0), A1 = make_float4(0,0,0,0), A2 = make_float4(0,0,0,0);
    float St = 0.f, S1al = 0.f, S1g = 0.f, S2ar = 0.f, S2g = 0.f;

    int row0 = blockIdx.x * 64;
    int rend = min(row0 + 64, N);
#pragma unroll 2
    for (int r = row0 + w; r < rend; r += 8) {
        size_t off = ((size_t)(b * N + r)) * 32 + lane;
        float4 a  = reinterpret_cast<const float4*>(addr)[off];
        float4 vt = reinterpret_cast<const float4*>(tg)[off];
        float4 v1 = reinterpret_cast<const float4*>(c1)[off];
        float4 v2 = reinterpret_cast<const float4*>(c2)[off];
        // 8 independent reductions
        float dp  = wsum(dot4(a, qp));
        float db  = wsum(dot4(a, qb));
        float d1p = wsum(dot4(v1, qp));
        float x1  = wsum(dot4(v1, qal));
        float n1  = wsum(dot4(v1, v1));
        float d2p = wsum(dot4(v2, qp));
        float x2  = wsum(dot4(v2, qar));
        float n2  = wsum(dot4(v2, v2));

        float nr = g_nrm[b * N + r];
        float alr = dp / fmaxf(nr * np, EPSF);
        float alpha = (alr > EPSF) ? alr : 0.f;
        float ia = 1.f - alpha;
        float cs4 = db / fmaxf(nr * nb, EPSF);

        float du1 = ia * d1p + alpha * kalp;
        float nu1 = sqrtf(fmaxf(ia*ia*n1 + 2.f*ia*alpha*x1 + alpha*alpha*kalal, 0.f));
        float s1 = du1 / fmaxf(nu1 * np, EPSF);
        float du2 = ia * d2p + alpha * karp;
        float nu2 = sqrtf(fmaxf(ia*ia*n2 + 2.f*ia*alpha*x2 + alpha*alpha*karar, 0.f));
        float s2 = du2 / fmaxf(nu2 * np, EPSF);

        if (lane == 0) {
            int bn = b * N + r;
            g_alp[bn] = alpha; g_s1[bn] = s1; g_s2[bn] = s2; g_cs4[bn] = cs4;
        }
        // vector parts (data terms only)
        float w1 = cs4 * (1.f - s1) * ia;
        float w2 = cs4 * (1.f - s2) * ia;
        acc4(At, cs4 * ia, vt);
        acc4(A1, w1, v1);
        acc4(A2, w2, v2);
        // scalar parts (q-vector coefficients)
        St   += cs4 * alpha;
        S1al += cs4 * (1.f - s1) * alpha;
        S1g  += cs4 * s1;
        S2ar += cs4 * (1.f - s2) * alpha;
        S2g  += cs4 * s2;
    }
    // epilogue: fold in q-vector terms
    float4 qtag = reinterpret_cast<const float4*>(&g_vec[4][b][0])[lane];
    float4 qarg = reinterpret_cast<const float4*>(&g_vec[1][b][0])[lane];
    acc4(At, St, qtag);
    acc4(A1, S1al, qal); acc4(A1, S1g, qarg);
    acc4(A2, S2ar, qar); acc4(A2, S2g, qarg);

    __shared__ float s[3][128];
    for (int j = threadIdx.x; j < 3 * 128; j += 256) (&s[0][0])[j] = 0.f;
    __syncthreads();
    int base = lane * 4;
    atomicAdd(&s[0][base+0], At.x); atomicAdd(&s[0][base+1], At.y); atomicAdd(&s[0][base+2], At.z); atomicAdd(&s[0][base+3], At.w);
    atomicAdd(&s[1][base+0], A1.x); atomicAdd(&s[1][base+1], A1.y); atomicAdd(&s[1][base+2], A1.z); atomicAdd(&s[1][base+3], A1.w);
    atomicAdd(&s[2][base+0], A2.x); atomicAdd(&s[2][base+1], A2.y); atomicAdd(&s[2][base+2], A2.z); atomicAdd(&s[2][base+3], A2.w);
    __syncthreads();
    if (threadIdx.x < 128) {
        atomicAdd(&g_vec[7][b][threadIdx.x], s[0][threadIdx.x]); // b_tag
        atomicAdd(&g_vec[8][b][threadIdx.x], s[1][threadIdx.x]); // b_l
        atomicAdd(&g_vec[9][b][threadIdx.x], s[2][threadIdx.x]); // b_r
    }
}

// ============ K3: reconstruct rows from inputs + insert(at, b_*) + closed-form GC ============
__global__ void __launch_bounds__(256) k_stage3(
    const float* __restrict__ tg, const float* __restrict__ c1, const float* __restrict__ c2,
    const float* __restrict__ zv, const int* __restrict__ gsp,
    float* __restrict__ ot, float* __restrict__ o1, float* __restrict__ o2,
    int B, int N)
{
    int i = blockIdx.x * blockDim.x + threadIdx.x;   // float4 index
    int total = B * N * 32;
    if (i >= total) return;
    int d4 = i & 31;
    int bn = i >> 5;
    int b = bn / N;
    float a1 = g_cs1[bn]; a1 = (a1 > EPSF) ? a1 : 0.f;
    float cf = g_cs2[bn]; cf = (cf > EPSF) ? cf : 0.f;
    float cp = g_alp[bn];
    float cb = g_cs4[bn]; cb = (cb > EPSF) ? cb : 0.f;
    float s1 = g_s1[bn], s2 = g_s2[bn];
    float base = (1.f - cf) * (1.f - cp) * (1.f - cb);
    int g = *gsp;
    float P = 1.f;
    for (int k = 0; k < g; k++) P *= base;
    float ia1 = 1.f - a1, icp = 1.f - cp, iP = 1.f - P;
    float4 z    = reinterpret_cast<const float4*>(zv)[d4];
    float4 qarg = reinterpret_cast<const float4*>(&g_vec[1][b][0])[d4];
    float4 qtag = reinterpret_cast<const float4*>(&g_vec[4][b][0])[d4];
    float4 qal  = reinterpret_cast<const float4*>(&g_vec[5][b][0])[d4];
    float4 qar  = reinterpret_cast<const float4*>(&g_vec[6][b][0])[d4];
    float4 bt   = reinterpret_cast<const float4*>(&g_vec[7][b][0])[d4];
    float4 bl   = reinterpret_cast<const float4*>(&g_vec[8][b][0])[d4];
    float4 br   = reinterpret_cast<const float4*>(&g_vec[9][b][0])[d4];

    float4 t = reinterpret_cast<const float4*>(tg)[i];
    t = mix4(icp, t, cp, qtag);
    t = mix4(ia1, t, a1, bt);
    reinterpret_cast<float4*>(ot)[i] = mix4(P, t, iP, z);

    t = reinterpret_cast<const float4*>(c1)[i];
    t = mix4(icp, t, cp, qal);
    t = mix4(1.f - s1, t, s1, qarg);
    t = mix4(ia1, t, a1, bl);
    reinterpret_cast<float4*>(o1)[i] = mix4(P, t, iP, z);

    t = reinterpret_cast<const float4*>(c2)[i];
    t = mix4(icp, t, cp, qar);
    t = mix4(1.f - s2, t, s2, qarg);
    t = mix4(ia1, t, a1, br);
    reinterpret_cast<float4*>(o2)[i] = mix4(P, t, iP, z);
}

// ============ launch ============
extern "C" void kernel_launch(void* const* d_in, const int* in_sizes, int n_in,
                              void* d_out, int out_size)
{
    const float* at   = (const float*)d_in[0];
    const float* addr = (const float*)d_in[1];
    const float* tg   = (const float*)d_in[2];
    const float* c1   = (const float*)d_in[3];
    const float* c2   = (const float*)d_in[4];
    const float* zv   = (const float*)d_in[5];
    const int*   gs   = (const int*)d_in[6];

    int D = in_sizes[5];
    int B = in_sizes[0] / D;
    int N = in_sizes[1] / in_sizes[0];

    size_t stride = (size_t)B * N * D;
    float* ot = (float*)d_out;
    float* o1 = ot + stride;
    float* o2 = o1 + stride;

    k_zero<<<(10 * BMAX * 128 + 255) / 256, 256>>>();

    dim3 grid((N + 63) / 64, B);
    k_stage0<<<grid, 256>>>(at, addr, c1, c2, N);
    k_stage1<<<grid, 256>>>(addr, tg, c1, c2, N);
    k_stage2<<<grid, 256>>>(addr, tg, c1, c2, N);

    int tot4 = B * N * (D / 4);
    k_stage3<<<(tot4 + 255) / 256, 256>>>(tg, c1, c2, zv, gs, ot, o1, o2, B, N);

    (void)n_in; (void)out_size;
}